// round 4
// baseline (speedup 1.0000x reference)
#include <cuda_runtime.h>
#include <cuda_bf16.h>
#include <math.h>

// Problem constants
#define Bn   16
#define Nn   1024
#define DIN  128
#define DOUT 32
#define ROWS (Bn*Nn)           // 16384
#define NEGV (-9e15f)

// ---------------- scratch (single __device__ buffer, ~164 MB) ----------------
#define O_HIN   0UL                      // 16384*128
#define O_H0    2097152UL                // 16384*128
#define O_FCWT  4194304UL                // 128*128
#define O_V1    4210688UL                // 256
#define O_E1S   4210944UL                // 16384
#define O_E1D   4227328UL                // 16384
#define O_ATT   4243712UL                // 16*1024*1024
#define O_T     21020928UL               // 16384*128
#define O_H1    23118080UL               // 16384*1024
#define O_WH2   39895296UL               // 16384*32
#define O_E2S   40419584UL               // 16384
#define O_E2D   40435968UL               // 16384
#define O_H2    40452352UL               // 16384*32
#define O_H3    40976640UL               // 16*1024
#define BUF_TOTAL 40993024UL

__device__ float g_buf[BUF_TOTAL];

__device__ __forceinline__ float warp_sum(float v) {
    #pragma unroll
    for (int o = 16; o > 0; o >>= 1) v += __shfl_down_sync(0xffffffffu, v, o);
    return v;
}
__device__ __forceinline__ float warp_max(float v) {
    #pragma unroll
    for (int o = 16; o > 0; o >>= 1) v = fmaxf(v, __shfl_down_sync(0xffffffffu, v, o));
    return v;
}

// ---------------- concat(x,l) -> hin [16384,128] ----------------
__global__ void concat_kernel(const float* __restrict__ x, const float* __restrict__ l,
                              float* __restrict__ hin) {
    int i = blockIdx.x * 256 + threadIdx.x;           // over 16384*128
    int r = i >> 7, c = i & 127;
    hin[i] = (c < 64) ? x[r * 64 + c] : l[r * 64 + (c - 64)];
}

// ---------------- fcwT[i][o] = fc_w[o][i] ----------------
__global__ void transpose128_kernel(const float* __restrict__ w, float* __restrict__ wt) {
    int idx = blockIdx.x * 256 + threadIdx.x;         // over 128*128
    int i = idx >> 7, o = idx & 127;
    wt[i * 128 + o] = w[o * 128 + i];
}

// ---------------- tiled fp32 GEMM: C = act(A@B + bias) ----------------
// A [M,K] row-major, B [K,N] row-major, C [M,N]. Optional batch (grid.z) via strides.
// BM=128, BK=16, BN_/TN_ templated. 256 threads, each computes 8 x TN_.
// act: 0 none, 1 relu, 2 elu
#define BM  128
#define BKT 16

template<int BN_, int TN_>
__global__ __launch_bounds__(256) void gemm_kernel(
    const float* __restrict__ A, const float* __restrict__ B, float* __restrict__ C,
    int M, int N, int K,
    long long sA, long long sB, long long sC,
    const float* __restrict__ bias, int act)
{
    __shared__ float As[BKT][BM + 4];
    __shared__ float Bs[BKT][BN_];
    int batch = blockIdx.z;
    A += (long long)batch * sA;
    B += (long long)batch * sB;
    C += (long long)batch * sC;
    int bm = blockIdx.y * BM, bn = blockIdx.x * BN_;
    int tid = threadIdx.x;
    int tx = tid & 15, ty = tid >> 4;

    float acc[8][TN_];
    #pragma unroll
    for (int i = 0; i < 8; i++)
        #pragma unroll
        for (int j = 0; j < TN_; j++) acc[i][j] = 0.f;

    for (int k0 = 0; k0 < K; k0 += BKT) {
        // load A tile: 128x16 floats = 512 float4, 2 per thread
        #pragma unroll
        for (int r = 0; r < 2; r++) {
            int q = tid + r * 256;
            int m = q >> 2;
            int kq = (q & 3) * 4;
            float4 v = make_float4(0.f, 0.f, 0.f, 0.f);
            if (bm + m < M)
                v = *(const float4*)&A[(long long)(bm + m) * K + k0 + kq];
            As[kq + 0][m] = v.x; As[kq + 1][m] = v.y;
            As[kq + 2][m] = v.z; As[kq + 3][m] = v.w;
        }
        // load B tile: 16 x BN_ floats = 4*BN_ float4
        #pragma unroll
        for (int q = tid; q < 4 * BN_; q += 256) {
            int k  = q / (BN_ / 4);
            int nq = (q % (BN_ / 4)) * 4;
            float4 v = make_float4(0.f, 0.f, 0.f, 0.f);
            if (bn + nq < N)
                v = *(const float4*)&B[(long long)(k0 + k) * N + bn + nq];
            *(float4*)&Bs[k][nq] = v;
        }
        __syncthreads();
        #pragma unroll
        for (int kk = 0; kk < BKT; kk++) {
            float a[8], b[TN_];
            float4 a0 = *(const float4*)&As[kk][ty * 8];
            float4 a1 = *(const float4*)&As[kk][ty * 8 + 4];
            a[0]=a0.x; a[1]=a0.y; a[2]=a0.z; a[3]=a0.w;
            a[4]=a1.x; a[5]=a1.y; a[6]=a1.z; a[7]=a1.w;
            #pragma unroll
            for (int j4 = 0; j4 < TN_; j4 += 4) {
                float4 bb = *(const float4*)&Bs[kk][tx * TN_ + j4];
                b[j4+0]=bb.x; b[j4+1]=bb.y; b[j4+2]=bb.z; b[j4+3]=bb.w;
            }
            #pragma unroll
            for (int i = 0; i < 8; i++)
                #pragma unroll
                for (int j = 0; j < TN_; j++)
                    acc[i][j] = fmaf(a[i], b[j], acc[i][j]);
        }
        __syncthreads();
    }
    #pragma unroll
    for (int i = 0; i < 8; i++) {
        int m = bm + ty * 8 + i;
        if (m >= M) continue;
        #pragma unroll
        for (int j = 0; j < TN_; j++) {
            int n = bn + tx * TN_ + j;
            if (n >= N) continue;
            float v = acc[i][j];
            if (bias) v += bias[n];
            if (act == 1) v = fmaxf(v, 0.f);
            else if (act == 2) v = (v > 0.f) ? v : expm1f(v);
            C[(long long)m * N + n] = v;
        }
    }
}

// ---------------- v1[s|d] = W1 @ a1 halves (warp per output row) ----------------
__global__ void v1_kernel(const float* __restrict__ W1, const float* __restrict__ a1,
                          float* __restrict__ v1) {
    int warp = (blockIdx.x * blockDim.x + threadIdx.x) >> 5;
    int lane = threadIdx.x & 31;
    if (warp >= 128) return;
    float as = 0.f, ad = 0.f;
    for (int j = lane; j < 1024; j += 32) {
        float w = W1[warp * 1024 + j];
        as += w * a1[j];
        ad += w * a1[1024 + j];
    }
    as = warp_sum(as); ad = warp_sum(ad);
    if (lane == 0) { v1[warp] = as; v1[128 + warp] = ad; }
}

// ---------------- e1s/e1d = h0 . v1 (warp per row, ALL 128 cols) ----------------
__global__ void e1_kernel(const float* __restrict__ h0, const float* __restrict__ v1,
                          float* __restrict__ e1s, float* __restrict__ e1d) {
    int r = (blockIdx.x * 256 + threadIdx.x) >> 5;
    int lane = threadIdx.x & 31;
    if (r >= ROWS) return;
    float accs = 0.f, accd = 0.f;
    #pragma unroll
    for (int q = 0; q < 4; q++) {
        int c = q * 32 + lane;
        float h = h0[r * 128 + c];
        accs = fmaf(h, v1[c],       accs);
        accd = fmaf(h, v1[128 + c], accd);
    }
    accs = warp_sum(accs); accd = warp_sum(accd);
    if (lane == 0) { e1s[r] = accs; e1d[r] = accd; }
}

// ---------------- e2s/e2d = Wh2 . a2 halves (warp per row) ----------------
__global__ void e2_kernel(const float* __restrict__ wh2, const float* __restrict__ a2,
                          float* __restrict__ e2s, float* __restrict__ e2d) {
    int r = (blockIdx.x * 256 + threadIdx.x) >> 5;
    int lane = threadIdx.x & 31;
    if (r >= ROWS) return;
    float w = wh2[r * 32 + lane];
    float accs = w * a2[lane];
    float accd = w * a2[32 + lane];
    accs = warp_sum(accs); accd = warp_sum(accd);
    if (lane == 0) { e2s[r] = accs; e2d[r] = accd; }
}

// ---------------- masked leaky-relu softmax row: att[b,n,:] ----------------
// 256 threads/row; each thread holds 4 entries in registers (int4/float4 loads).
__global__ __launch_bounds__(256) void att_kernel(
    const float* __restrict__ es, const float* __restrict__ ed,
    const int* __restrict__ adj, float* __restrict__ att)
{
    int b = blockIdx.y, n = blockIdx.x;
    const int*   arow = adj + ((long long)b * Nn + n) * Nn;
    const float* edb  = ed + b * Nn;
    float esv = es[b * Nn + n];
    __shared__ float red[8];
    int tid  = threadIdx.x;
    int lane = tid & 31, wid = tid >> 5;
    int m0 = tid * 4;

    int4   a4 = *(const int4*)  &arow[m0];
    float4 e4 = *(const float4*)&edb[m0];
    float v[4];
    {
        int   am[4] = {a4.x, a4.y, a4.z, a4.w};
        float em[4] = {e4.x, e4.y, e4.z, e4.w};
        #pragma unroll
        for (int j = 0; j < 4; j++) {
            float t = esv + em[j];
            t = (t > 0.f) ? t : 0.2f * t;
            v[j] = (am[j] > 0) ? t : NEGV;
        }
    }

    float mx = fmaxf(fmaxf(v[0], v[1]), fmaxf(v[2], v[3]));
    mx = warp_max(mx);
    if (lane == 0) red[wid] = mx;
    __syncthreads();
    if (tid < 8) {
        float m = red[tid];
        #pragma unroll
        for (int o = 4; o > 0; o >>= 1) m = fmaxf(m, __shfl_down_sync(0xffu, m, o));
        if (tid == 0) red[0] = m;
    }
    __syncthreads();
    mx = red[0];

    float4 ex;
    ex.x = __expf(v[0] - mx);
    ex.y = __expf(v[1] - mx);
    ex.z = __expf(v[2] - mx);
    ex.w = __expf(v[3] - mx);
    float sm = (ex.x + ex.y) + (ex.z + ex.w);
    sm = warp_sum(sm);
    __syncthreads();
    if (lane == 0) red[wid] = sm;
    __syncthreads();
    if (tid < 8) {
        float s = red[tid];
        #pragma unroll
        for (int o = 4; o > 0; o >>= 1) s += __shfl_down_sync(0xffu, s, o);
        if (tid == 0) red[0] = s;
    }
    __syncthreads();
    float inv = 1.0f / red[0];

    ex.x *= inv; ex.y *= inv; ex.z *= inv; ex.w *= inv;
    *(float4*)&att[((long long)b * Nn + n) * Nn + m0] = ex;
}

// ---------------- fc1: out[16,1024] = relu(flat[16,32768] @ w[1024,32768]^T + b) --
__global__ __launch_bounds__(128) void fc1_kernel(
    const float* __restrict__ flat, const float* __restrict__ w,
    const float* __restrict__ bias, float* __restrict__ out)
{
    const int NO = 8;
    int o0 = blockIdx.x * NO;
    int tid = threadIdx.x;                   // 128 threads
    float acc[16][NO];
    #pragma unroll
    for (int b = 0; b < 16; b++)
        #pragma unroll
        for (int oo = 0; oo < NO; oo++) acc[b][oo] = 0.f;

    for (int k4 = tid; k4 < 32768 / 4; k4 += 128) {
        int k = k4 * 4;
        float4 wv[NO];
        #pragma unroll
        for (int oo = 0; oo < NO; oo++)
            wv[oo] = *(const float4*)&w[(long long)(o0 + oo) * 32768 + k];
        #pragma unroll
        for (int b = 0; b < 16; b++) {
            float4 f = *(const float4*)&flat[b * 32768 + k];
            #pragma unroll
            for (int oo = 0; oo < NO; oo++) {
                acc[b][oo] = fmaf(f.x, wv[oo].x, acc[b][oo]);
                acc[b][oo] = fmaf(f.y, wv[oo].y, acc[b][oo]);
                acc[b][oo] = fmaf(f.z, wv[oo].z, acc[b][oo]);
                acc[b][oo] = fmaf(f.w, wv[oo].w, acc[b][oo]);
            }
        }
    }
    __shared__ float red[4][16][NO];
    int wid = tid >> 5, lane = tid & 31;
    #pragma unroll
    for (int b = 0; b < 16; b++)
        #pragma unroll
        for (int oo = 0; oo < NO; oo++) {
            float v = warp_sum(acc[b][oo]);
            if (lane == 0) red[wid][b][oo] = v;
        }
    __syncthreads();
    if (tid < 128) {
        int b = tid >> 3, oo = tid & 7;
        float s = red[0][b][oo] + red[1][b][oo] + red[2][b][oo] + red[3][b][oo];
        s += bias[o0 + oo];
        s = fmaxf(s, 0.f);
        out[b * Nn + o0 + oo] = s;
    }
}

// ---------------- fc2: y[16,32] = h3 @ fc2_w^T + b ----------------
__global__ void fc2_kernel(const float* __restrict__ h3, const float* __restrict__ w,
                           const float* __restrict__ bias, float* __restrict__ out) {
    int tid = threadIdx.x;                    // 512 threads
    int b = tid >> 5, d = tid & 31;
    float acc = 0.f;
    for (int o = 0; o < 1024; o++)
        acc = fmaf(h3[b * 1024 + o], w[d * 1024 + o], acc);
    out[b * 32 + d] = acc + bias[d];
}

// ---------------- launcher ----------------
extern "C" void kernel_launch(void* const* d_in, const int* in_sizes, int n_in,
                              void* d_out, int out_size) {
    const float* x     = (const float*)d_in[0];
    const float* l     = (const float*)d_in[1];
    const int*   adj   = (const int*)  d_in[2];
    const float* fc_w  = (const float*)d_in[3];
    const float* fc_b  = (const float*)d_in[4];
    const float* W1    = (const float*)d_in[5];
    const float* a1    = (const float*)d_in[6];
    const float* W2    = (const float*)d_in[7];
    const float* a2    = (const float*)d_in[8];
    const float* fc1_w = (const float*)d_in[9];
    const float* fc1_b = (const float*)d_in[10];
    const float* fc2_w = (const float*)d_in[11];
    const float* fc2_b = (const float*)d_in[12];
    float* out = (float*)d_out;

    void* bufp = nullptr;
    cudaGetSymbolAddress(&bufp, g_buf);
    float* buf  = (float*)bufp;
    float* hin  = buf + O_HIN;
    float* h0   = buf + O_H0;
    float* fcwT = buf + O_FCWT;
    float* v1   = buf + O_V1;
    float* e1s  = buf + O_E1S;
    float* e1d  = buf + O_E1D;
    float* att  = buf + O_ATT;
    float* t    = buf + O_T;
    float* h1   = buf + O_H1;
    float* wh2  = buf + O_WH2;
    float* e2s  = buf + O_E2S;
    float* e2d  = buf + O_E2D;
    float* h2   = buf + O_H2;
    float* h3   = buf + O_H3;

    // h0 = relu(concat(x,l) @ fc_w^T + fc_b)
    concat_kernel<<<ROWS * 128 / 256, 256>>>(x, l, hin);
    transpose128_kernel<<<64, 256>>>(fc_w, fcwT);
    gemm_kernel<128, 8><<<dim3(1, 128, 1), 256>>>(hin, fcwT, h0, ROWS, 128, 128,
                                                  0, 0, 0, fc_b, 1);
    // layer 1 (Wh1 factored out): e1 = h0 @ (W1 @ a1-halves)
    v1_kernel<<<16, 256>>>(W1, a1, v1);
    e1_kernel<<<ROWS / 8, 256>>>(h0, v1, e1s, e1d);
    att_kernel<<<dim3(Nn, Bn), 256>>>(e1s, e1d, adj, att);
    // t = att @ h0 (batched), h1 = elu(t @ W1)
    gemm_kernel<128, 8><<<dim3(1, 8, Bn), 256>>>(att, h0, t, Nn, 128, Nn,
                                                 (long long)Nn * Nn, (long long)Nn * 128,
                                                 (long long)Nn * 128, nullptr, 0);
    gemm_kernel<128, 8><<<dim3(8, 128, 1), 256>>>(t, W1, h1, ROWS, Nn, 128,
                                                  0, 0, 0, nullptr, 2);
    // layer 2
    gemm_kernel<64, 4><<<dim3(1, 128, 1), 256>>>(h1, W2, wh2, ROWS, DOUT, Nn,
                                                 0, 0, 0, nullptr, 0);
    e2_kernel<<<ROWS / 8, 256>>>(wh2, a2, e2s, e2d);
    att_kernel<<<dim3(Nn, Bn), 256>>>(e2s, e2d, adj, att);
    gemm_kernel<64, 4><<<dim3(1, 8, Bn), 256>>>(att, wh2, h2, Nn, DOUT, Nn,
                                                (long long)Nn * Nn, (long long)Nn * DOUT,
                                                (long long)Nn * DOUT, nullptr, 2);
    // output MLP
    fc1_kernel<<<128, 128>>>(h2, fc1_w, fc1_b, h3);
    fc2_kernel<<<1, 512>>>(h3, fc2_w, fc2_b, out);
}

// round 5
// speedup vs baseline: 1.4118x; 1.4118x over previous
#include <cuda_runtime.h>
#include <cuda_bf16.h>
#include <math.h>
#include <stdint.h>

// Problem constants
#define Bn   16
#define Nn   1024
#define DIN  128
#define DOUT 32
#define ROWS (Bn*Nn)           // 16384

// ---------------- scratch ----------------
#define O_HIN   0UL                      // 16384*128
#define O_H0    2097152UL                // 16384*128
#define O_FCWT  4194304UL                // 128*128
#define O_V1    4210688UL                // 256
#define O_E1S   4210944UL                // 16384
#define O_E1D   4227328UL                // 16384
#define O_ATT   4243712UL                // 16*1024*1024
#define O_T     21020928UL               // 16384*128
#define O_H1    23118080UL               // 16384*1024
#define O_WH2   39895296UL               // 16384*32
#define O_E2S   40419584UL               // 16384
#define O_E2D   40435968UL               // 16384
#define O_H2    40452352UL               // 16384*32
#define O_H3    40976640UL               // 16*1024
#define O_EXA   40993024UL               // 16384  exp(ed)
#define O_EXB   41009408UL               // 16384  exp(0.2 ed)
#define BUF_TOTAL 41025792UL

__device__ float g_buf[BUF_TOTAL];

__device__ __forceinline__ float warp_sum(float v) {
    #pragma unroll
    for (int o = 16; o > 0; o >>= 1) v += __shfl_down_sync(0xffffffffu, v, o);
    return v;
}

__device__ __forceinline__ uint32_t f2tf32(float x) {
    uint32_t r;
    asm("cvt.rna.tf32.f32 %0, %1;" : "=r"(r) : "f"(x));
    return r;
}

// ---------------- concat(x,l) -> hin [16384,128] ----------------
__global__ void concat_kernel(const float* __restrict__ x, const float* __restrict__ l,
                              float* __restrict__ hin) {
    int i = blockIdx.x * 256 + threadIdx.x;
    int r = i >> 7, c = i & 127;
    hin[i] = (c < 64) ? x[r * 64 + c] : l[r * 64 + (c - 64)];
}

// ---------------- fcwT[i][o] = fc_w[o][i] ----------------
__global__ void transpose128_kernel(const float* __restrict__ w, float* __restrict__ wt) {
    int idx = blockIdx.x * 256 + threadIdx.x;
    int i = idx >> 7, o = idx & 127;
    wt[i * 128 + o] = w[o * 128 + i];
}

// ---------------- tf32 tensor-core GEMM ----------------
// C = act(A@B + bias). A [M,K] rm, B [K,N] rm, C [M,N]. Batched via grid.z+strides.
// M % BM == 0, N % BN == 0, K % 32 == 0 (guaranteed by all call sites).
// act: 0 none, 1 relu, 2 elu
template<int WARPS_M, int WARPS_N, int MT, int NT>
__global__ __launch_bounds__(WARPS_M * WARPS_N * 32) void gemm_tc(
    const float* __restrict__ A, const float* __restrict__ B, float* __restrict__ C,
    int M, int N, int K,
    long long sA, long long sB, long long sC,
    const float* __restrict__ bias, int act)
{
    constexpr int BM = WARPS_M * MT * 16;
    constexpr int BN = WARPS_N * NT * 8;
    constexpr int BK = 32;
    constexpr int NTHR = WARPS_M * WARPS_N * 32;

    __shared__ uint32_t As[BK][BM + 4];
    __shared__ uint32_t Bs[BK][BN + 4];

    int batch = blockIdx.z;
    A += (long long)batch * sA;
    B += (long long)batch * sB;
    C += (long long)batch * sC;

    int tid  = threadIdx.x;
    int lane = tid & 31, warp = tid >> 5;
    int wm = warp % WARPS_M, wn = warp / WARPS_M;
    int bm = blockIdx.y * BM, bn = blockIdx.x * BN;

    float c[MT][NT][4];
    #pragma unroll
    for (int i = 0; i < MT; i++)
        #pragma unroll
        for (int j = 0; j < NT; j++)
            #pragma unroll
            for (int r = 0; r < 4; r++) c[i][j][r] = 0.f;

    for (int k0 = 0; k0 < K; k0 += BK) {
        // A tile: BM x 32 (transpose into k-major, tf32-converted)
        #pragma unroll
        for (int q = tid; q < BM * 8; q += NTHR) {
            int m  = q >> 3;
            int k4 = (q & 7) * 4;
            float4 v = *(const float4*)&A[(long long)(bm + m) * K + k0 + k4];
            As[k4 + 0][m] = f2tf32(v.x);
            As[k4 + 1][m] = f2tf32(v.y);
            As[k4 + 2][m] = f2tf32(v.z);
            As[k4 + 3][m] = f2tf32(v.w);
        }
        // B tile: 32 x BN
        #pragma unroll
        for (int q = tid; q < BN * 8; q += NTHR) {
            int k  = q / (BN / 4);
            int n4 = (q % (BN / 4)) * 4;
            float4 v = *(const float4*)&B[(long long)(k0 + k) * N + bn + n4];
            uint4 w;
            w.x = f2tf32(v.x); w.y = f2tf32(v.y);
            w.z = f2tf32(v.z); w.w = f2tf32(v.w);
            *(uint4*)&Bs[k][n4] = w;
        }
        __syncthreads();

        #pragma unroll
        for (int s = 0; s < 4; s++) {
            int kb   = s * 8 + (lane & 3);
            int row0 = wm * MT * 16 + (lane >> 2);
            int col0 = wn * NT * 8 + (lane >> 2);
            uint32_t a[MT][4], b[NT][2];
            #pragma unroll
            for (int i = 0; i < MT; i++) {
                a[i][0] = As[kb    ][row0 + i * 16    ];
                a[i][1] = As[kb    ][row0 + i * 16 + 8];
                a[i][2] = As[kb + 4][row0 + i * 16    ];
                a[i][3] = As[kb + 4][row0 + i * 16 + 8];
            }
            #pragma unroll
            for (int j = 0; j < NT; j++) {
                b[j][0] = Bs[kb    ][col0 + j * 8];
                b[j][1] = Bs[kb + 4][col0 + j * 8];
            }
            #pragma unroll
            for (int i = 0; i < MT; i++)
                #pragma unroll
                for (int j = 0; j < NT; j++)
                    asm volatile(
                        "mma.sync.aligned.m16n8k8.row.col.f32.tf32.tf32.f32 "
                        "{%0,%1,%2,%3}, {%4,%5,%6,%7}, {%8,%9}, {%0,%1,%2,%3};\n"
                        : "+f"(c[i][j][0]), "+f"(c[i][j][1]),
                          "+f"(c[i][j][2]), "+f"(c[i][j][3])
                        : "r"(a[i][0]), "r"(a[i][1]), "r"(a[i][2]), "r"(a[i][3]),
                          "r"(b[j][0]), "r"(b[j][1]));
        }
        __syncthreads();
    }

    // epilogue
    #pragma unroll
    for (int i = 0; i < MT; i++) {
        int r_lo = bm + wm * MT * 16 + i * 16 + (lane >> 2);
        #pragma unroll
        for (int j = 0; j < NT; j++) {
            int cl = bn + wn * NT * 8 + j * 8 + (lane & 3) * 2;
            float bz0 = bias ? bias[cl]     : 0.f;
            float bz1 = bias ? bias[cl + 1] : 0.f;
            float v0 = c[i][j][0] + bz0, v1 = c[i][j][1] + bz1;
            float v2 = c[i][j][2] + bz0, v3 = c[i][j][3] + bz1;
            if (act == 1) {
                v0 = fmaxf(v0, 0.f); v1 = fmaxf(v1, 0.f);
                v2 = fmaxf(v2, 0.f); v3 = fmaxf(v3, 0.f);
            } else if (act == 2) {
                v0 = (v0 > 0.f) ? v0 : expm1f(v0);
                v1 = (v1 > 0.f) ? v1 : expm1f(v1);
                v2 = (v2 > 0.f) ? v2 : expm1f(v2);
                v3 = (v3 > 0.f) ? v3 : expm1f(v3);
            }
            *(float2*)&C[(long long)r_lo * N + cl]       = make_float2(v0, v1);
            *(float2*)&C[(long long)(r_lo + 8) * N + cl] = make_float2(v2, v3);
        }
    }
}

// ---------------- v1[s|d] = W1 @ a1 halves (warp per output row) ----------------
__global__ void v1_kernel(const float* __restrict__ W1, const float* __restrict__ a1,
                          float* __restrict__ v1) {
    int warp = (blockIdx.x * blockDim.x + threadIdx.x) >> 5;
    int lane = threadIdx.x & 31;
    if (warp >= 128) return;
    float as = 0.f, ad = 0.f;
    for (int j = lane; j < 1024; j += 32) {
        float w = W1[warp * 1024 + j];
        as += w * a1[j];
        ad += w * a1[1024 + j];
    }
    as = warp_sum(as); ad = warp_sum(ad);
    if (lane == 0) { v1[warp] = as; v1[128 + warp] = ad; }
}

// ---------------- e1s/e1d = h0 . v1 (warp per row, all 128 cols) ----------------
__global__ void e1_kernel(const float* __restrict__ h0, const float* __restrict__ v1,
                          float* __restrict__ e1s, float* __restrict__ e1d) {
    int r = (blockIdx.x * 256 + threadIdx.x) >> 5;
    int lane = threadIdx.x & 31;
    if (r >= ROWS) return;
    float accs = 0.f, accd = 0.f;
    #pragma unroll
    for (int q = 0; q < 4; q++) {
        int c = q * 32 + lane;
        float h = h0[r * 128 + c];
        accs = fmaf(h, v1[c],       accs);
        accd = fmaf(h, v1[128 + c], accd);
    }
    accs = warp_sum(accs); accd = warp_sum(accd);
    if (lane == 0) { e1s[r] = accs; e1d[r] = accd; }
}

// ---------------- e2s/e2d = Wh2 . a2 halves (warp per row) ----------------
__global__ void e2_kernel(const float* __restrict__ wh2, const float* __restrict__ a2,
                          float* __restrict__ e2s, float* __restrict__ e2d) {
    int r = (blockIdx.x * 256 + threadIdx.x) >> 5;
    int lane = threadIdx.x & 31;
    if (r >= ROWS) return;
    float w = wh2[r * 32 + lane];
    float accs = w * a2[lane];
    float accd = w * a2[32 + lane];
    accs = warp_sum(accs); accd = warp_sum(accd);
    if (lane == 0) { e2s[r] = accs; e2d[r] = accd; }
}

// ---------------- exps of ed: EA = exp(ed), EB = exp(0.2 ed) ----------------
__global__ void expd_kernel(const float* __restrict__ ed,
                            float* __restrict__ EA, float* __restrict__ EB) {
    int i = blockIdx.x * 256 + threadIdx.x;
    if (i >= ROWS) return;
    float d = ed[i];
    EA[i] = __expf(d);
    EB[i] = __expf(0.2f * d);
}

// ---------------- factored masked softmax row ----------------
// exp(lrelu(es+ed)) == max(exp(es)*exp(ed), exp(0.2 es)*exp(0.2 ed)); shift-free.
__global__ __launch_bounds__(256) void attf_kernel(
    const float* __restrict__ es,
    const float* __restrict__ EA, const float* __restrict__ EB,
    const int* __restrict__ adj, float* __restrict__ att)
{
    int b = blockIdx.y, n = blockIdx.x;
    const int*   arow = adj + ((long long)b * Nn + n) * Nn;
    const float* ea   = EA + b * Nn;
    const float* eb   = EB + b * Nn;
    float esv = es[b * Nn + n];
    float A1 = __expf(esv);
    float A2 = __expf(0.2f * esv);
    __shared__ float red[8];
    int tid  = threadIdx.x;
    int lane = tid & 31, wid = tid >> 5;
    int m0 = tid * 4;

    int4   a4  = *(const int4*)  &arow[m0];
    float4 e1v = *(const float4*)&ea[m0];
    float4 e2v = *(const float4*)&eb[m0];
    float v[4];
    v[0] = (a4.x > 0) ? fmaxf(A1 * e1v.x, A2 * e2v.x) : 0.f;
    v[1] = (a4.y > 0) ? fmaxf(A1 * e1v.y, A2 * e2v.y) : 0.f;
    v[2] = (a4.z > 0) ? fmaxf(A1 * e1v.z, A2 * e2v.z) : 0.f;
    v[3] = (a4.w > 0) ? fmaxf(A1 * e1v.w, A2 * e2v.w) : 0.f;

    float sm = (v[0] + v[1]) + (v[2] + v[3]);
    sm = warp_sum(sm);
    if (lane == 0) red[wid] = sm;
    __syncthreads();
    if (tid < 8) {
        float s = red[tid];
        #pragma unroll
        for (int o = 4; o > 0; o >>= 1) s += __shfl_down_sync(0xffu, s, o);
        if (tid == 0) red[0] = s;
    }
    __syncthreads();
    float inv = 1.0f / red[0];

    float4 o4 = make_float4(v[0] * inv, v[1] * inv, v[2] * inv, v[3] * inv);
    *(float4*)&att[((long long)b * Nn + n) * Nn + m0] = o4;
}

// ---------------- fc1: out[16,1024] = relu(flat @ w^T + b) ----------------
__global__ __launch_bounds__(128) void fc1_kernel(
    const float* __restrict__ flat, const float* __restrict__ w,
    const float* __restrict__ bias, float* __restrict__ out)
{
    const int NO = 8;
    int o0 = blockIdx.x * NO;
    int tid = threadIdx.x;
    float acc[16][NO];
    #pragma unroll
    for (int b = 0; b < 16; b++)
        #pragma unroll
        for (int oo = 0; oo < NO; oo++) acc[b][oo] = 0.f;

    for (int k4 = tid; k4 < 32768 / 4; k4 += 128) {
        int k = k4 * 4;
        float4 wv[NO];
        #pragma unroll
        for (int oo = 0; oo < NO; oo++)
            wv[oo] = *(const float4*)&w[(long long)(o0 + oo) * 32768 + k];
        #pragma unroll
        for (int b = 0; b < 16; b++) {
            float4 f = *(const float4*)&flat[b * 32768 + k];
            #pragma unroll
            for (int oo = 0; oo < NO; oo++) {
                acc[b][oo] = fmaf(f.x, wv[oo].x, acc[b][oo]);
                acc[b][oo] = fmaf(f.y, wv[oo].y, acc[b][oo]);
                acc[b][oo] = fmaf(f.z, wv[oo].z, acc[b][oo]);
                acc[b][oo] = fmaf(f.w, wv[oo].w, acc[b][oo]);
            }
        }
    }
    __shared__ float red[4][16][NO];
    int wid = tid >> 5, lane = tid & 31;
    #pragma unroll
    for (int b = 0; b < 16; b++)
        #pragma unroll
        for (int oo = 0; oo < NO; oo++) {
            float v = warp_sum(acc[b][oo]);
            if (lane == 0) red[wid][b][oo] = v;
        }
    __syncthreads();
    if (tid < 128) {
        int b = tid >> 3, oo = tid & 7;
        float s = red[0][b][oo] + red[1][b][oo] + red[2][b][oo] + red[3][b][oo];
        s += bias[o0 + oo];
        s = fmaxf(s, 0.f);
        out[b * Nn + o0 + oo] = s;
    }
}

// ---------------- fc2: y[16,32] = h3 @ fc2_w^T + b ----------------
__global__ void fc2_kernel(const float* __restrict__ h3, const float* __restrict__ w,
                           const float* __restrict__ bias, float* __restrict__ out) {
    int tid = threadIdx.x;
    int b = tid >> 5, d = tid & 31;
    float acc = 0.f;
    for (int o = 0; o < 1024; o++)
        acc = fmaf(h3[b * 1024 + o], w[d * 1024 + o], acc);
    out[b * 32 + d] = acc + bias[d];
}

// ---------------- launcher ----------------
extern "C" void kernel_launch(void* const* d_in, const int* in_sizes, int n_in,
                              void* d_out, int out_size) {
    const float* x     = (const float*)d_in[0];
    const float* l     = (const float*)d_in[1];
    const int*   adj   = (const int*)  d_in[2];
    const float* fc_w  = (const float*)d_in[3];
    const float* fc_b  = (const float*)d_in[4];
    const float* W1    = (const float*)d_in[5];
    const float* a1    = (const float*)d_in[6];
    const float* W2    = (const float*)d_in[7];
    const float* a2    = (const float*)d_in[8];
    const float* fc1_w = (const float*)d_in[9];
    const float* fc1_b = (const float*)d_in[10];
    const float* fc2_w = (const float*)d_in[11];
    const float* fc2_b = (const float*)d_in[12];
    float* out = (float*)d_out;

    void* bufp = nullptr;
    cudaGetSymbolAddress(&bufp, g_buf);
    float* buf  = (float*)bufp;
    float* hin  = buf + O_HIN;
    float* h0   = buf + O_H0;
    float* fcwT = buf + O_FCWT;
    float* v1   = buf + O_V1;
    float* e1s  = buf + O_E1S;
    float* e1d  = buf + O_E1D;
    float* att  = buf + O_ATT;
    float* t    = buf + O_T;
    float* h1   = buf + O_H1;
    float* wh2  = buf + O_WH2;
    float* e2s  = buf + O_E2S;
    float* e2d  = buf + O_E2D;
    float* h2   = buf + O_H2;
    float* h3   = buf + O_H3;
    float* exa  = buf + O_EXA;
    float* exb  = buf + O_EXB;

    // h0 = relu(concat(x,l) @ fc_w^T + fc_b)
    concat_kernel<<<ROWS * 128 / 256, 256>>>(x, l, hin);
    transpose128_kernel<<<64, 256>>>(fc_w, fcwT);
    gemm_tc<2, 4, 4, 4><<<dim3(1, 128, 1), 256>>>(hin, fcwT, h0, ROWS, 128, 128,
                                                  0, 0, 0, fc_b, 1);
    // layer 1
    v1_kernel<<<16, 256>>>(W1, a1, v1);
    e1_kernel<<<ROWS / 8, 256>>>(h0, v1, e1s, e1d);
    expd_kernel<<<ROWS / 256, 256>>>(e1d, exa, exb);
    attf_kernel<<<dim3(Nn, Bn), 256>>>(e1s, exa, exb, adj, att);
    gemm_tc<2, 4, 4, 4><<<dim3(1, 8, Bn), 256>>>(att, h0, t, Nn, 128, Nn,
                                                 (long long)Nn * Nn, (long long)Nn * 128,
                                                 (long long)Nn * 128, nullptr, 0);
    gemm_tc<2, 4, 4, 4><<<dim3(8, 128, 1), 256>>>(t, W1, h1, ROWS, Nn, 128,
                                                  0, 0, 0, nullptr, 2);
    // layer 2
    gemm_tc<8, 1, 1, 4><<<dim3(1, 128, 1), 256>>>(h1, W2, wh2, ROWS, DOUT, Nn,
                                                  0, 0, 0, nullptr, 0);
    e2_kernel<<<ROWS / 8, 256>>>(wh2, a2, e2s, e2d);
    expd_kernel<<<ROWS / 256, 256>>>(e2d, exa, exb);
    attf_kernel<<<dim3(Nn, Bn), 256>>>(e2s, exa, exb, adj, att);
    gemm_tc<8, 1, 1, 4><<<dim3(1, 8, Bn), 256>>>(att, wh2, h2, Nn, DOUT, Nn,
                                                 (long long)Nn * Nn, (long long)Nn * DOUT,
                                                 (long long)Nn * DOUT, nullptr, 2);
    // output MLP
    fc1_kernel<<<128, 128>>>(h2, fc1_w, fc1_b, h3);
    fc2_kernel<<<1, 512>>>(h3, fc2_w, fc2_b, out);
}